// round 2
// baseline (speedup 1.0000x reference)
#include <cuda_runtime.h>
#include <cstdint>
#include <math.h>

// Problem constants
#define BATCH   131072
#define DIM     256
#define KTOT    1024      // 3*256 (z concat) + 256 (noise_z, 0.1 folded into weights)
#define NOUT    32        // 16 route logits + 16 noise pre-softplus
#define NP      16
#define KSEL    4

// Tiling
#define ROWS    128       // rows per block
#define KC      64        // K-chunk staged in smem
#define SMS     68        // padded smem stride for input tile

// Combined weights, built on-device each call (deterministic, no allocation)
__device__ float g_wT[KTOT * NOUT];   // [k][o] layout, o in [0,32)
__device__ float g_biasC[NOUT];

// ---------------------------------------------------------------------------
// Pre-kernel: Wc[o][k<768]   = sum_d Wsel[p,d] * W_proj[d,k]   (fp64 accum)
//             Wc[o][768+d]   = 0.1 * Wsel[p,d]
//             biasC[o]       = b_sel[p] + sum_d Wsel[p,d]*b_proj[d]
// ---------------------------------------------------------------------------
__global__ void build_combined(const float* __restrict__ W_proj,
                               const float* __restrict__ b_proj,
                               const float* __restrict__ W_route,
                               const float* __restrict__ b_route,
                               const float* __restrict__ W_noise,
                               const float* __restrict__ b_noise) {
    int idx = blockIdx.x * blockDim.x + threadIdx.x;
    if (idx >= KTOT * NOUT) return;
    int o = idx & 31;          // output column 0..31
    int k = idx >> 5;          // 0..1023
    int p = o & 15;
    const float* Wsel = (o < 16) ? W_route : W_noise;

    float val;
    if (k < 768) {
        double acc = 0.0;
        #pragma unroll 8
        for (int d = 0; d < 256; d++)
            acc += (double)Wsel[p * 256 + d] * (double)W_proj[d * 768 + k];
        val = (float)acc;
    } else {
        val = 0.1f * Wsel[p * 256 + (k - 768)];
    }
    g_wT[k * 32 + o] = val;

    if (idx < 32) {  // one thread per output column builds the bias
        double acc = (o < 16) ? (double)b_route[p] : (double)b_noise[p];
        for (int d = 0; d < 256; d++)
            acc += (double)Wsel[p * 256 + d] * (double)b_proj[d];
        g_biasC[o] = (float)acc;
    }
}

// ---------------------------------------------------------------------------
// Main fused kernel: combined GEMM [ROWS,1024]x[1024,32] + softplus + noise +
// softmax(16) + top-4 + scatter + gather, all in one pass.
// Block: 256 threads, thread tile = 4 rows x 4 outputs.
// ---------------------------------------------------------------------------
__global__ __launch_bounds__(256) void router_main(
    const float* __restrict__ z_n,   const float* __restrict__ z_sea,
    const float* __restrict__ z_trend, const float* __restrict__ noise_z,
    const float* __restrict__ noise_r, const int* __restrict__ patch_cand,
    float* __restrict__ out)
{
    __shared__ float in_s[ROWS][SMS];   // 128 x 68 floats = 34.8 KB
    __shared__ float w_s[KC][NOUT];     // 64 x 32 floats  =  8 KB

    const int tid  = threadIdx.x;
    const int row0 = blockIdx.x * ROWS;
    const int og   = tid & 7;    // output group: outputs og*4 .. og*4+3
    const int rg   = tid >> 3;   // row group:    rows    rg*4 .. rg*4+3

    float acc[4][4];
    #pragma unroll
    for (int r = 0; r < 4; r++)
        #pragma unroll
        for (int o = 0; o < 4; o++) acc[r][o] = 0.0f;

    for (int c = 0; c < 16; c++) {
        // chunk c covers k = c*64 .. c*64+63; each chunk lives in exactly one
        // of the 4 source arrays (256/64 = 4 chunks per source)
        const float* src = (c < 8) ? ((c < 4) ? z_n : z_sea)
                                   : ((c < 12) ? z_trend : noise_z);
        const int koff = (c & 3) * KC;

        // Stage input tile: 128 rows x 64 floats (coalesced 256B runs)
        #pragma unroll
        for (int i = 0; i < 8; i++) {
            int idx = tid + i * 256;            // 0..2047
            int r   = idx >> 4;
            int c4  = idx & 15;
            float4 v = __ldg((const float4*)(src + (size_t)(row0 + r) * DIM
                                                 + koff + c4 * 4));
            *(float4*)&in_s[r][c4 * 4] = v;
        }
        // Stage weight tile: 64 x 32 floats (L2-resident after first blocks)
        #pragma unroll
        for (int i = 0; i < 2; i++) {
            int idx = tid + i * 256;            // 0..511
            int wk  = idx >> 3;
            int wo  = idx & 7;
            float4 v = __ldg((const float4*)(g_wT + (size_t)(c * KC + wk) * 32
                                                  + wo * 4));
            *(float4*)&w_s[wk][wo * 4] = v;
        }
        __syncthreads();

        #pragma unroll 8
        for (int k = 0; k < KC; k += 4) {
            float a[4][4];   // a[r][kk]
            #pragma unroll
            for (int r = 0; r < 4; r++)
                *(float4*)a[r] = *(const float4*)&in_s[rg * 4 + r][k];
            float w[4][4];   // w[kk][o]
            #pragma unroll
            for (int kk = 0; kk < 4; kk++)
                *(float4*)w[kk] = *(const float4*)&w_s[k + kk][og * 4];
            #pragma unroll
            for (int kk = 0; kk < 4; kk++)
                #pragma unroll
                for (int r = 0; r < 4; r++)
                    #pragma unroll
                    for (int o = 0; o < 4; o++)
                        acc[r][o] = fmaf(a[r][kk], w[kk][o], acc[r][o]);
        }
        __syncthreads();
    }

    // Stash per-row results (overlay in_s: last sync above guards the reuse)
    float (*res)[33] = (float(*)[33])&in_s[0][0];   // 128 x 33 = 16.9 KB
    #pragma unroll
    for (int r = 0; r < 4; r++)
        #pragma unroll
        for (int o = 0; o < 4; o++)
            res[rg * 4 + r][og * 4 + o] = acc[r][o];
    __syncthreads();

    // Epilogue: one thread per row (threads 0..127)
    if (tid < ROWS) {
        const int grow = row0 + tid;
        float v[32];
        #pragma unroll
        for (int o = 0; o < 32; o++) v[o] = res[tid][o];

        float nr[16];
        #pragma unroll
        for (int i = 0; i < 4; i++) {
            float4 t = __ldg((const float4*)(noise_r + (size_t)grow * 16 + i * 4));
            nr[i * 4 + 0] = t.x; nr[i * 4 + 1] = t.y;
            nr[i * 4 + 2] = t.z; nr[i * 4 + 3] = t.w;
        }

        float logit[16];
        #pragma unroll
        for (int p = 0; p < 16; p++) {
            float pre = v[16 + p] + g_biasC[16 + p];
            // numerically stable softplus = max(x,0) + log1p(exp(-|x|))
            float sp  = fmaxf(pre, 0.0f) + log1pf(expf(-fabsf(pre)));
            logit[p]  = v[p] + g_biasC[p] + nr[p] * sp;
        }

        // softmax over 16
        float m = logit[0];
        #pragma unroll
        for (int p = 1; p < 16; p++) m = fmaxf(m, logit[p]);
        float e[16], s = 0.0f;
        #pragma unroll
        for (int p = 0; p < 16; p++) { e[p] = expf(logit[p] - m); s += e[p]; }
        float w[16];
        #pragma unroll
        for (int p = 0; p < 16; p++) w[p] = e[p] / s;

        // top-4 with tie-break to lower index (strict >)
        float sp_out[16];
        #pragma unroll
        for (int p = 0; p < 16; p++) sp_out[p] = 0.0f;
        int   idxs[4];
        unsigned mask = 0u;
        #pragma unroll
        for (int kk = 0; kk < 4; kk++) {
            float best = -1.0f; int bi = 0;
            #pragma unroll
            for (int p = 0; p < 16; p++) {
                bool free = ((mask >> p) & 1u) == 0u;
                if (free && w[p] > best) { best = w[p]; bi = p; }
            }
            mask |= 1u << bi;
            idxs[kk] = bi;
            sp_out[bi] = best;
        }

        // outputs: [sparse_routing B*16 | selected_patches B*4 | topk_idx B*4]
        float* sp_ptr = out + (size_t)grow * 16;
        #pragma unroll
        for (int i = 0; i < 4; i++) {
            float4 t = make_float4(sp_out[i * 4 + 0], sp_out[i * 4 + 1],
                                   sp_out[i * 4 + 2], sp_out[i * 4 + 3]);
            *(float4*)(sp_ptr + i * 4) = t;
        }
        float* pp = out + (size_t)BATCH * 16 + (size_t)grow * 4;
        float* ip = out + (size_t)BATCH * 20 + (size_t)grow * 4;
        #pragma unroll
        for (int kk = 0; kk < 4; kk++) {
            pp[kk] = (float)__ldg(patch_cand + idxs[kk]);
            ip[kk] = (float)idxs[kk];
        }
    }
}

// ---------------------------------------------------------------------------
extern "C" void kernel_launch(void* const* d_in, const int* in_sizes, int n_in,
                              void* d_out, int out_size) {
    const float* z_n        = (const float*)d_in[0];
    const float* z_sea      = (const float*)d_in[1];
    const float* z_trend    = (const float*)d_in[2];
    const float* noise_z    = (const float*)d_in[3];
    const float* noise_r    = (const float*)d_in[4];
    const int*   patch_cand = (const int*)  d_in[5];
    const float* W_proj     = (const float*)d_in[6];
    const float* b_proj     = (const float*)d_in[7];
    const float* W_route    = (const float*)d_in[8];
    const float* b_route    = (const float*)d_in[9];
    const float* W_noise    = (const float*)d_in[10];
    const float* b_noise    = (const float*)d_in[11];
    float* out = (float*)d_out;

    build_combined<<<(KTOT * NOUT + 255) / 256, 256>>>(
        W_proj, b_proj, W_route, b_route, W_noise, b_noise);

    router_main<<<BATCH / ROWS, 256>>>(
        z_n, z_sea, z_trend, noise_z, noise_r, patch_cand, out);
}